// round 1
// baseline (speedup 1.0000x reference)
#include <cuda_runtime.h>
#include <cstdint>

#define S_TOK 4096
#define MDIM  1024
#define NEXP  8
#define CAP   1024

#define BM 128
#define BN 128
#define BK 32

// ---------------- scratch (device globals; no allocations allowed) ----------
__device__ int   g_idx0[S_TOK];
__device__ float g_wtop[S_TOK];     // top-1 gate (pre-drop)
__device__ float g_wscale[S_TOK];   // top-1 gate (0 if dropped)
__device__ int   g_perm[NEXP * CAP];
__device__ int   g_cnt[NEXP];
__device__ float g_me[NEXP];
__device__ float g_ce[NEXP];

// ---------------- helpers ---------------------------------------------------
__device__ __forceinline__ uint32_t f2tf32(float v) {
    uint32_t r;
    asm("cvt.rna.tf32.f32 %0, %1;" : "=r"(r) : "f"(v));
    return r;
}

#define MMA_TF32(c, a, b)                                                      \
    asm volatile(                                                              \
        "mma.sync.aligned.m16n8k8.row.col.f32.tf32.tf32.f32 "                  \
        "{%0,%1,%2,%3},{%4,%5,%6,%7},{%8,%9},{%0,%1,%2,%3};\n"                 \
        : "+f"((c)[0]), "+f"((c)[1]), "+f"((c)[2]), "+f"((c)[3])               \
        : "r"((a)[0]), "r"((a)[1]), "r"((a)[2]), "r"((a)[3]),                  \
          "r"((b)[0]), "r"((b)[1]))

// ---------------- kernel 1: zero output + stats -----------------------------
__global__ void init_kernel(float* __restrict__ out, long total) {
    long n4 = total >> 2;
    float4 z = make_float4(0.f, 0.f, 0.f, 0.f);
    long stride = (long)gridDim.x * blockDim.x;
    for (long j = (long)blockIdx.x * blockDim.x + threadIdx.x; j < n4; j += stride)
        reinterpret_cast<float4*>(out)[j] = z;
    if (blockIdx.x == 0 && threadIdx.x == 0)
        for (long j = n4 << 2; j < total; j++) out[j] = 0.f;
    if (blockIdx.x == 0 && threadIdx.x < NEXP) {
        g_me[threadIdx.x] = 0.f;
        g_ce[threadIdx.x] = 0.f;
    }
}

// ---------------- kernel 2: gating (logits, softmax, top-1, me/ce) ----------
__global__ void gate_kernel(const float* __restrict__ x,
                            const float* __restrict__ wg) {
    __shared__ float me_s[NEXP];
    __shared__ float ce_s[NEXP];
    int tid = threadIdx.x;
    if (tid < NEXP) { me_s[tid] = 0.f; ce_s[tid] = 0.f; }
    __syncthreads();

    int warp = tid >> 5, lane = tid & 31;
    int s = blockIdx.x * 8 + warp;   // warp per token, 8 tokens / block

    float acc[NEXP];
#pragma unroll
    for (int e = 0; e < NEXP; e++) acc[e] = 0.f;

    const float4* xr = reinterpret_cast<const float4*>(x + (size_t)s * MDIM);
#pragma unroll
    for (int i = 0; i < 8; i++) {
        int k4 = i * 32 + lane;            // float4 index within the row
        float4 xv = xr[k4];
#pragma unroll
        for (int e = 0; e < NEXP; e++) {
            float4 wv = reinterpret_cast<const float4*>(wg + e * MDIM)[k4];
            acc[e] += xv.x * wv.x + xv.y * wv.y + xv.z * wv.z + xv.w * wv.w;
        }
    }
#pragma unroll
    for (int e = 0; e < NEXP; e++) {
#pragma unroll
        for (int off = 16; off > 0; off >>= 1)
            acc[e] += __shfl_xor_sync(0xffffffffu, acc[e], off);
    }

    if (lane == 0) {
        float mx = acc[0];
        int am = 0;
#pragma unroll
        for (int e = 1; e < NEXP; e++)
            if (acc[e] > mx) { mx = acc[e]; am = e; }   // first-max => lowest idx on ties
        float g[NEXP];
        float sum = 0.f;
#pragma unroll
        for (int e = 0; e < NEXP; e++) { g[e] = expf(acc[e] - mx); sum += g[e]; }
        float inv = 1.f / sum;
        g_idx0[s] = am;
        g_wtop[s] = g[am] * inv;
#pragma unroll
        for (int e = 0; e < NEXP; e++) atomicAdd(&me_s[e], g[e] * inv);
        atomicAdd(&ce_s[am], 1.f);
    }
    __syncthreads();
    if (tid < NEXP) {
        atomicAdd(&g_me[tid], me_s[tid]);
        atomicAdd(&g_ce[tid], ce_s[tid]);
    }
}

// ---------------- kernel 3: stable per-expert scan + perm + loss ------------
__global__ void scan_kernel(float* __restrict__ out, int write_loss) {
    __shared__ unsigned char sidx[S_TOK];
    __shared__ int counts[256][9];   // pad to 9 to break bank conflicts
    int tid = threadIdx.x;

    for (int i = tid; i < S_TOK; i += 256)
        sidx[i] = (unsigned char)g_idx0[i];
    __syncthreads();

    int base = tid * 16;
    int c8[NEXP];
#pragma unroll
    for (int e = 0; e < NEXP; e++) c8[e] = 0;
#pragma unroll
    for (int j = 0; j < 16; j++) c8[sidx[base + j]]++;
#pragma unroll
    for (int e = 0; e < NEXP; e++) counts[tid][e] = c8[e];
    __syncthreads();

    if (tid < NEXP) {
        int run = 0;
        for (int t = 0; t < 256; t++) {
            int v = counts[t][tid];
            counts[t][tid] = run;   // exclusive prefix
            run += v;
        }
        g_cnt[tid] = run < CAP ? run : CAP;
    }
    __syncthreads();

    int off[NEXP];
#pragma unroll
    for (int e = 0; e < NEXP; e++) off[e] = counts[tid][e];
#pragma unroll
    for (int j = 0; j < 16; j++) {
        int s2 = base + j;
        int e = sidx[s2];
        int c = off[e]++;
        if (c < CAP) {
            g_perm[e * CAP + c] = s2;
            g_wscale[s2] = g_wtop[s2];
        } else {
            g_wscale[s2] = 0.f;   // dropped: output row stays zero
        }
    }

    if (tid == 0 && write_loss) {
        float l = 0.f;
#pragma unroll
        for (int e = 0; e < NEXP; e++) l += g_me[e] * g_ce[e];
        out[(size_t)S_TOK * MDIM] =
            l * ((float)NEXP / ((float)S_TOK * (float)S_TOK));
    }
}

// ---------------- kernel 4: gathered grouped GEMM (tf32 mma.sync) -----------
__global__ void __launch_bounds__(256)
moe_gemm(const float* __restrict__ x, const float* __restrict__ we,
         float* __restrict__ out) {
    __shared__ uint32_t As[BM][36];    // [m][k], pad 36 -> conflict-free frags
    __shared__ uint32_t Bs[BK][132];   // [k][n], pad 132
    __shared__ int   toks[BM];
    __shared__ float wsh[BM];

    int e = blockIdx.z, rt = blockIdx.y;
    int count = g_cnt[e];
    if (rt * BM >= count) return;
    int nb = blockIdx.x * BN;
    int tid = threadIdx.x;

    if (tid < BM) {
        int slot = rt * BM + tid;
        int s = (slot < count) ? g_perm[e * CAP + slot] : -1;
        toks[tid] = s;
        wsh[tid] = (s >= 0) ? g_wscale[s] : 0.f;
    }
    __syncthreads();

    // global-load thread mapping
    int arow = tid >> 3;          // 0..31
    int acol = (tid & 7) * 4;     // 0..28
    int brow = tid >> 5;          // 0..7
    int bcol = (tid & 31) * 4;    // 0..124
    const float* weB = we + (size_t)e * MDIM * MDIM;

    int atok[4];
#pragma unroll
    for (int p = 0; p < 4; p++) atok[p] = toks[arow + 32 * p];

    float4 aReg[4], bReg[4];
    auto loadA = [&](int kt) {
#pragma unroll
        for (int p = 0; p < 4; p++) {
            if (atok[p] >= 0)
                aReg[p] = *reinterpret_cast<const float4*>(
                    x + (size_t)atok[p] * MDIM + kt * BK + acol);
            else
                aReg[p] = make_float4(0.f, 0.f, 0.f, 0.f);
        }
    };
    auto loadB = [&](int kt) {
#pragma unroll
        for (int p = 0; p < 4; p++)
            bReg[p] = *reinterpret_cast<const float4*>(
                weB + (size_t)(kt * BK + brow + 8 * p) * MDIM + nb + bcol);
    };
    auto stsAB = [&]() {
#pragma unroll
        for (int p = 0; p < 4; p++) {
            uint32_t* da = &As[arow + 32 * p][acol];
            da[0] = f2tf32(aReg[p].x); da[1] = f2tf32(aReg[p].y);
            da[2] = f2tf32(aReg[p].z); da[3] = f2tf32(aReg[p].w);
            uint32_t* db = &Bs[brow + 8 * p][bcol];
            db[0] = f2tf32(bReg[p].x); db[1] = f2tf32(bReg[p].y);
            db[2] = f2tf32(bReg[p].z); db[3] = f2tf32(bReg[p].w);
        }
    };

    int warp = tid >> 5, lane = tid & 31;
    int gid = lane >> 2, tg = lane & 3;
    int wr = (warp & 1) * 64;       // warp row base (2 warps along M)
    int wc = (warp >> 1) * 32;      // warp col base (4 warps along N)

    float acc[4][4][4];
#pragma unroll
    for (int mi = 0; mi < 4; mi++)
#pragma unroll
        for (int ni = 0; ni < 4; ni++)
#pragma unroll
            for (int r = 0; r < 4; r++) acc[mi][ni][r] = 0.f;

    const int NKT = MDIM / BK;   // 32
    loadA(0); loadB(0);
    for (int kt = 0; kt < NKT; kt++) {
        stsAB();
        __syncthreads();
        if (kt + 1 < NKT) { loadA(kt + 1); loadB(kt + 1); }
#pragma unroll
        for (int ks = 0; ks < 4; ks++) {
            int kk = ks * 8;
            uint32_t a[4][4], b[4][2];
#pragma unroll
            for (int mi = 0; mi < 4; mi++) {
                int r = wr + mi * 16 + gid;
                a[mi][0] = As[r][kk + tg];
                a[mi][1] = As[r + 8][kk + tg];
                a[mi][2] = As[r][kk + tg + 4];
                a[mi][3] = As[r + 8][kk + tg + 4];
            }
#pragma unroll
            for (int ni = 0; ni < 4; ni++) {
                int cc = wc + ni * 8 + gid;
                b[ni][0] = Bs[kk + tg][cc];
                b[ni][1] = Bs[kk + tg + 4][cc];
            }
#pragma unroll
            for (int mi = 0; mi < 4; mi++)
#pragma unroll
                for (int ni = 0; ni < 4; ni++)
                    MMA_TF32(acc[mi][ni], a[mi], b[ni]);
        }
        __syncthreads();
    }

    // epilogue: out[s, nb + col] = w[s] * acc
#pragma unroll
    for (int mi = 0; mi < 4; mi++) {
#pragma unroll
        for (int half = 0; half < 2; half++) {
            int r = wr + mi * 16 + gid + 8 * half;
            int slot = rt * BM + r;
            if (slot < count) {
                int s = toks[r];
                float w = wsh[r];
                float* o = out + (size_t)s * MDIM + nb + wc + tg * 2;
#pragma unroll
                for (int ni = 0; ni < 4; ni++) {
                    float2 v;
                    v.x = acc[mi][ni][half * 2 + 0] * w;
                    v.y = acc[mi][ni][half * 2 + 1] * w;
                    *reinterpret_cast<float2*>(o + ni * 8) = v;
                }
            }
        }
    }
}

// ---------------- launch -----------------------------------------------------
extern "C" void kernel_launch(void* const* d_in, const int* in_sizes, int n_in,
                              void* d_out, int out_size) {
    const float* x  = (const float*)d_in[0];
    const float* wg = (const float*)d_in[1];
    const float* we = (const float*)d_in[2];
    float* out = (float*)d_out;

    init_kernel<<<1024, 256>>>(out, (long)out_size);
    gate_kernel<<<S_TOK / 8, 256>>>(x, wg);
    scan_kernel<<<1, 256>>>(out, (long)out_size > (long)S_TOK * MDIM ? 1 : 0);
    dim3 g(MDIM / BN, CAP / BM, NEXP);
    moe_gemm<<<g, 256>>>(x, we, out);
}